// round 14
// baseline (speedup 1.0000x reference)
#include <cuda_runtime.h>
#include <cuda_fp16.h>
#include <cstdint>

// Sinkhorn-Knopp, fp16 matrix, ONE sweep/iter, register double-buffered LDG.
// R14 = R13 with the iteration loop restructured to process TWO 2-row groups
// per __syncthreads (7 barriers/CTA instead of 14): phase1(x)+phase1(y) ->
// publish 64 partials -> one barrier -> one widened butterfly -> phase2(x)
// + reload(x) -> phase2(y) + reload(y).
//   E' = 1024*exp(-10*C) fp16, evh = ev/32 fp16.
//   phase1: rp_h2 += E'*evh -> 32*rowsum; eu = 32(d+eps)/rs
//   phase2: cacc_h2 += eu*E' (fp16 partial colsums)
//   col_reduce: ev = (s+eps)*1024/sum(partials); evh = ev/32
//   final: P = (eu/1024)*E'*ev == eu*E*ev exactly (powers of 2)

#define NN 8192
#define NC4 (NN / 8)                 // 1024 uint4 chunks per row
#define GROWS 2
#define NGROUPS (NN / GROWS)         // 4096
#define NCTAS 296                    // 2 CTAs/SM
#define NTHR 512
#define EPS 1e-6f
#define ESCALE 1024.0f
#define PERSIST_ROWS 5632

__device__ __align__(16) __half g_E[(size_t)NN * NN];          // 128 MB
__device__ __align__(16) float  g_eu[NN];                      // eu/1024 (final)
__device__ __align__(16) float  g_ev[NN];                      // fp32 ev (final)
__device__ __align__(16) __half g_evh[NN];                     // ev/32 (hot loop)
__device__ __align__(16) __half g_parth[(size_t)NCTAS * NN];   // 4.85 MB fp16

// ---- L2 evict_last policy helpers (neutral but harmless; kept from R13) ---
__device__ __forceinline__ uint64_t policy_evict_last() {
    uint64_t pol;
    asm("createpolicy.fractional.L2::evict_last.b64 %0, 1.0;" : "=l"(pol));
    return pol;
}
__device__ __forceinline__ uint4 ldg_pol(const uint4* p, uint64_t pol) {
    uint4 v;
    asm volatile("ld.global.L2::cache_hint.v4.b32 {%0,%1,%2,%3}, [%4], %5;"
                 : "=r"(v.x), "=r"(v.y), "=r"(v.z), "=r"(v.w)
                 : "l"(p), "l"(pol));
    return v;
}
__device__ __forceinline__ void stg_pol(uint4* p, uint4 v, uint64_t pol) {
    asm volatile("st.global.L2::cache_hint.v4.b32 [%0], {%1,%2,%3,%4}, %5;"
                 :: "l"(p), "r"(v.x), "r"(v.y), "r"(v.z), "r"(v.w), "l"(pol)
                 : "memory");
}

// FMA-only exp for x in [-15, 0]
__device__ __forceinline__ float fast_exp_neg(float x) {
    const float LOG2E = 1.4426950408889634f;
    float t = x * LOG2E;
    float n = rintf(t);
    float f = t - n;
    float p = 1.5403530393381608e-4f;
    p = fmaf(p, f, 1.3333558146428443e-3f);
    p = fmaf(p, f, 9.6181291076284770e-3f);
    p = fmaf(p, f, 5.5504108664821580e-2f);
    p = fmaf(p, f, 2.4022650695910070e-1f);
    p = fmaf(p, f, 6.9314718055994530e-1f);
    p = fmaf(p, f, 1.0f);
    return p * __int_as_float(((int)n + 127) << 23);
}

// ---------------------------------------------------------------------------
__global__ void precompute_kernel(const float* __restrict__ C) {
    size_t g = (size_t)blockIdx.x * blockDim.x + threadIdx.x;
    const float4* C4 = reinterpret_cast<const float4*>(C);
    float4 c0 = C4[2 * g];
    float4 c1 = C4[2 * g + 1];
    uint4 o;
    __half2* h = reinterpret_cast<__half2*>(&o);
    h[0] = __floats2half2_rn(ESCALE * fast_exp_neg(-10.0f * c0.x),
                             ESCALE * fast_exp_neg(-10.0f * c0.y));
    h[1] = __floats2half2_rn(ESCALE * fast_exp_neg(-10.0f * c0.z),
                             ESCALE * fast_exp_neg(-10.0f * c0.w));
    h[2] = __floats2half2_rn(ESCALE * fast_exp_neg(-10.0f * c1.x),
                             ESCALE * fast_exp_neg(-10.0f * c1.y));
    h[3] = __floats2half2_rn(ESCALE * fast_exp_neg(-10.0f * c1.z),
                             ESCALE * fast_exp_neg(-10.0f * c1.w));
    uint4* dst = reinterpret_cast<uint4*>(g_E) + g;
    int row = (int)(g >> 10);
    if (row < PERSIST_ROWS) {
        stg_pol(dst, o, policy_evict_last());
    } else {
        *dst = o;
    }
    if (g < NN) {
        const float E1 = 2.718281828459045f;     // exp(v0), v0 = 1
        g_ev[g]  = E1;
        g_evh[g] = __float2half_rn(E1 * 0.03125f);
    }
}

// ---------------------------------------------------------------------------
// Fused iteration: 296 CTAs x 512 threads, 2 CTAs/SM. Two 2-row groups per
// barrier. Thread t owns chunks t and t+512 of each row it touches.
// ---------------------------------------------------------------------------
__global__ void __launch_bounds__(NTHR, 2)
iter_kernel(const float* __restrict__ d) {
    __shared__ float wpart[128];      // [2 parities][64]

    const int tid  = threadIdx.x;
    const int wid  = tid >> 5;
    const int lane = tid & 31;
    const int cta  = blockIdx.x;
    const int ng   = (NGROUPS - cta + NCTAS - 1) / NCTAS;      // 13 or 14

    const uint4* Eg  = reinterpret_cast<const uint4*>(g_E);
    const uint4* EVH = reinterpret_cast<const uint4*>(g_evh);
    const uint64_t pol = policy_evict_last();

    // ev/32 for this thread's 16 columns (8 half2 regs, loop-invariant)
    __half2 va2[4], vb2[4];
    {
        uint4 v = __ldg(EVH + tid);
        const __half2* hv = reinterpret_cast<const __half2*>(&v);
#pragma unroll
        for (int k = 0; k < 4; ++k) va2[k] = hv[k];
        v = __ldg(EVH + tid + 512);
        hv = reinterpret_cast<const __half2*>(&v);
#pragma unroll
        for (int k = 0; k < 4; ++k) vb2[k] = hv[k];
    }

    __half2 cacc[8];
#pragma unroll
    for (int k = 0; k < 8; ++k) cacc[k] = __float2half2_rn(0.0f);

    uint4 xA0, xB0, xA1, xB1;         // buffer for even groups
    uint4 yA0, yB0, yA1, yB1;         // buffer for odd groups

    auto loadg = [&](int t, uint4& a0, uint4& b0, uint4& a1, uint4& b1) {
        const int grow0 = (cta + t * NCTAS) * GROWS;
        const uint4* s0 = Eg + (size_t)grow0 * NC4;
        const uint4* s1 = s0 + NC4;
        if (grow0 < PERSIST_ROWS) {
            a0 = ldg_pol(s0 + tid, pol);
            b0 = ldg_pol(s0 + tid + 512, pol);
            a1 = ldg_pol(s1 + tid, pol);
            b1 = ldg_pol(s1 + tid + 512, pol);
        } else {
            a0 = __ldcs(s0 + tid);
            b0 = __ldcs(s0 + tid + 512);
            a1 = __ldcs(s1 + tid);
            b1 = __ldcs(s1 + tid + 512);
        }
    };

    // phase 1 for one group held in (eA0,eB0,eA1,eB1): warp-reduced partials
    auto phase1 = [&](const uint4& eA0, const uint4& eB0,
                      const uint4& eA1, const uint4& eB1,
                      float& s0, float& s1) {
        const __half2* a0 = reinterpret_cast<const __half2*>(&eA0);
        const __half2* b0 = reinterpret_cast<const __half2*>(&eB0);
        const __half2* a1 = reinterpret_cast<const __half2*>(&eA1);
        const __half2* b1 = reinterpret_cast<const __half2*>(&eB1);
        __half2 rp0 = __float2half2_rn(0.0f);
        __half2 rp1 = __float2half2_rn(0.0f);
#pragma unroll
        for (int k = 0; k < 4; ++k) {
            rp0 = __hfma2(a0[k], va2[k], rp0);
            rp0 = __hfma2(b0[k], vb2[k], rp0);
            rp1 = __hfma2(a1[k], va2[k], rp1);
            rp1 = __hfma2(b1[k], vb2[k], rp1);
        }
        float2 f0 = __half22float2(rp0);
        float2 f1 = __half22float2(rp1);
        s0 = f0.x + f0.y;
        s1 = f1.x + f1.y;
#pragma unroll
        for (int o = 16; o > 0; o >>= 1) {
            s0 += __shfl_down_sync(0xFFFFFFFFu, s0, o);
            s1 += __shfl_down_sync(0xFFFFFFFFu, s1, o);
        }
    };

    // phase 2: accumulate one group into cacc with row factors u0, u1
    auto phase2 = [&](const uint4& eA0, const uint4& eB0,
                      const uint4& eA1, const uint4& eB1,
                      float eu0, float eu1) {
        const __half2* a0 = reinterpret_cast<const __half2*>(&eA0);
        const __half2* b0 = reinterpret_cast<const __half2*>(&eB0);
        const __half2* a1 = reinterpret_cast<const __half2*>(&eA1);
        const __half2* b1 = reinterpret_cast<const __half2*>(&eB1);
        __half2 u0 = __float2half2_rn(eu0);
        __half2 u1 = __float2half2_rn(eu1);
#pragma unroll
        for (int k = 0; k < 4; ++k) {
            cacc[k]     = __hfma2(a0[k], u0, cacc[k]);
            cacc[4 + k] = __hfma2(b0[k], u0, cacc[4 + k]);
            cacc[k]     = __hfma2(a1[k], u1, cacc[k]);
            cacc[4 + k] = __hfma2(b1[k], u1, cacc[4 + k]);
        }
    };

    // 16-lane butterfly pair: input v (rows r, r+1 packed in lane halves)
    auto butterfly2 = [&](float v, float& rs0, float& rs1) {
#pragma unroll
        for (int o = 1; o < 16; o <<= 1)
            v += __shfl_xor_sync(0xFFFFFFFFu, v, o);
        float w = __shfl_xor_sync(0xFFFFFFFFu, v, 16);
        rs0 = (lane < 16) ? v : w;
        rs1 = (lane < 16) ? w : v;
    };

    loadg(0, xA0, xB0, xA1, xB1);
    if (ng > 1) loadg(1, yA0, yB0, yA1, yB1);

    int t = 0;
    for (; t + 1 < ng; t += 2) {
        const int grow0 = (cta + t * NCTAS) * GROWS;         // rows of group t
        const int grow1 = grow0 + NCTAS * GROWS;             // rows of group t+1
        float* wp = wpart + ((t >> 1) & 1) * 64;

        float s0, s1, s2, s3;
        phase1(xA0, xB0, xA1, xB1, s0, s1);
        phase1(yA0, yB0, yA1, yB1, s2, s3);
        if (lane == 0) {
            wp[wid]      = s0;
            wp[16 + wid] = s1;
            wp[32 + wid] = s2;
            wp[48 + wid] = s3;
        }
        __syncthreads();              // ONE barrier per two groups

        float rs0, rs1, rs2, rs3;
        butterfly2(wp[lane],      rs0, rs1);
        butterfly2(wp[32 + lane], rs2, rs3);
        float eu0 = __fdividef((__ldg(d + grow0)     + EPS) * 32.0f, rs0);
        float eu1 = __fdividef((__ldg(d + grow0 + 1) + EPS) * 32.0f, rs1);
        float eu2 = __fdividef((__ldg(d + grow1)     + EPS) * 32.0f, rs2);
        float eu3 = __fdividef((__ldg(d + grow1 + 1) + EPS) * 32.0f, rs3);
        if (tid == 0) {
            g_eu[grow0]     = eu0 * (1.0f / 1024.0f);
            g_eu[grow0 + 1] = eu1 * (1.0f / 1024.0f);
            g_eu[grow1]     = eu2 * (1.0f / 1024.0f);
            g_eu[grow1 + 1] = eu3 * (1.0f / 1024.0f);
        }

        phase2(xA0, xB0, xA1, xB1, eu0, eu1);
        if (t + 2 < ng) loadg(t + 2, xA0, xB0, xA1, xB1);
        phase2(yA0, yB0, yA1, yB1, eu2, eu3);
        if (t + 3 < ng) loadg(t + 3, yA0, yB0, yA1, yB1);
    }

    if (t < ng) {                     // odd trailing group (in x buffer)
        const int grow0 = (cta + t * NCTAS) * GROWS;
        float* wp = wpart + ((t >> 1) & 1) * 64;
        float s0, s1;
        phase1(xA0, xB0, xA1, xB1, s0, s1);
        if (lane == 0) {
            wp[wid]      = s0;
            wp[16 + wid] = s1;
        }
        __syncthreads();
        float rs0, rs1;
        butterfly2(wp[lane], rs0, rs1);
        float eu0 = __fdividef((__ldg(d + grow0)     + EPS) * 32.0f, rs0);
        float eu1 = __fdividef((__ldg(d + grow0 + 1) + EPS) * 32.0f, rs1);
        if (tid == 0) {
            g_eu[grow0]     = eu0 * (1.0f / 1024.0f);
            g_eu[grow0 + 1] = eu1 * (1.0f / 1024.0f);
        }
        phase2(xA0, xB0, xA1, xB1, eu0, eu1);
    }

    // write fp16 partials (streaming stores)
    uint4 o0, o1;
    __half2* p0 = reinterpret_cast<__half2*>(&o0);
    __half2* p1 = reinterpret_cast<__half2*>(&o1);
#pragma unroll
    for (int k = 0; k < 4; ++k) { p0[k] = cacc[k]; p1[k] = cacc[4 + k]; }
    uint4* PH = reinterpret_cast<uint4*>(g_parth + (size_t)cta * NN);
    __stcs(PH + tid,       o0);
    __stcs(PH + tid + 512, o1);
}

// ---------------------------------------------------------------------------
// ev from fp16 partials: sum 296 partials in fp32, fixed order.
// grid = 32 CTAs x 256 threads; thread (slice 0..7, chunk 0..31).
// ---------------------------------------------------------------------------
__global__ void col_reduce_kernel(const float* __restrict__ s) {
    __shared__ float red[8][32][8];
    const int g     = threadIdx.x & 31;
    const int slice = threadIdx.x >> 5;
    const int chunk = blockIdx.x * 32 + g;       // 0..1023 (8 cols each)
    const uint4* PH = reinterpret_cast<const uint4*>(g_parth);
    float acc[8] = {0.f, 0.f, 0.f, 0.f, 0.f, 0.f, 0.f, 0.f};
#pragma unroll
    for (int k = 0; k < 37; ++k) {
        uint4 v = __ldcs(PH + (size_t)(slice * 37 + k) * NC4 + chunk);
        const __half2* h = reinterpret_cast<const __half2*>(&v);
#pragma unroll
        for (int m = 0; m < 4; ++m) {
            float2 f = __half22float2(h[m]);
            acc[2 * m]     += f.x;
            acc[2 * m + 1] += f.y;
        }
    }
#pragma unroll
    for (int m = 0; m < 8; ++m) red[slice][g][m] = acc[m];
    __syncthreads();
    if (slice == 0) {
        float t[8];
#pragma unroll
        for (int m = 0; m < 8; ++m) t[m] = red[0][g][m];
#pragma unroll
        for (int q = 1; q < 8; ++q)                 // fixed order
#pragma unroll
            for (int m = 0; m < 8; ++m) t[m] += red[q][g][m];
        const int j0 = chunk * 8;
        float ev[8];
#pragma unroll
        for (int m = 0; m < 8; ++m)
            ev[m] = (s[j0 + m] + EPS) * 1024.0f / t[m];
        float4* EV4 = reinterpret_cast<float4*>(g_ev + j0);
        EV4[0] = make_float4(ev[0], ev[1], ev[2], ev[3]);
        EV4[1] = make_float4(ev[4], ev[5], ev[6], ev[7]);
        uint4 hv;
        __half2* hp = reinterpret_cast<__half2*>(&hv);
#pragma unroll
        for (int m = 0; m < 4; ++m)
            hp[m] = __floats2half2_rn(ev[2 * m] * 0.03125f,
                                      ev[2 * m + 1] * 0.03125f);
        *reinterpret_cast<uint4*>(g_evh + j0) = hv;
    }
}

// ---------------------------------------------------------------------------
// Final: P_ij = (eu_i/1024) * E'_ij * ev_j   (fp32 eu/ev)
// ---------------------------------------------------------------------------
__global__ void final_kernel(float* __restrict__ out) {
    size_t idx = (size_t)blockIdx.x * blockDim.x + threadIdx.x;
    int row = (int)(idx / NC4);
    int c8  = (int)(idx % NC4);
    float u = g_eu[row];
    const float4* ev4 = reinterpret_cast<const float4*>(g_ev);
    float4 v0 = ev4[2 * c8];
    float4 v1 = ev4[2 * c8 + 1];
    uint4 e = __ldg(reinterpret_cast<const uint4*>(g_E) + idx);
    const __half2* hp = reinterpret_cast<const __half2*>(&e);
    float2 f0 = __half22float2(hp[0]);
    float2 f1 = __half22float2(hp[1]);
    float2 f2 = __half22float2(hp[2]);
    float2 f3 = __half22float2(hp[3]);
    float4 p0, p1;
    p0.x = u * f0.x * v0.x;  p0.y = u * f0.y * v0.y;
    p0.z = u * f1.x * v0.z;  p0.w = u * f1.y * v0.w;
    p1.x = u * f2.x * v1.x;  p1.y = u * f2.y * v1.y;
    p1.z = u * f3.x * v1.z;  p1.w = u * f3.y * v1.w;
    float4* O4 = reinterpret_cast<float4*>(out);
    O4[2 * idx]     = p0;
    O4[2 * idx + 1] = p1;
}

// ---------------------------------------------------------------------------
extern "C" void kernel_launch(void* const* d_in, const int* in_sizes, int n_in,
                              void* d_out, int out_size) {
    const float* C = (const float*)d_in[0];
    const float* d = (const float*)d_in[1];
    const float* s = (const float*)d_in[2];
    float* out = (float*)d_out;

    const int VBLOCKS = (NN * NC4) / 256;    // 32768

    precompute_kernel<<<VBLOCKS, 256>>>(C);

    for (int it = 0; it < 50; ++it) {
        iter_kernel<<<NCTAS, NTHR>>>(d);
        col_reduce_kernel<<<32, 256>>>(s);
    }

    final_kernel<<<VBLOCKS, 256>>>(out);
}

// round 15
// speedup vs baseline: 1.0863x; 1.0863x over previous
#include <cuda_runtime.h>
#include <cuda_fp16.h>
#include <cstdint>

// Sinkhorn-Knopp, fp16 matrix, ONE sweep/iter, register double-buffered LDG.
// R15 = R13 iter loop (proven best) + column reduction FUSED into the iter
// kernel tail: all 296 CTAs are co-resident (launch_bounds(512,2) on 148
// SMs), so CTAs 0..31 can wait on a device counter until every CTA has
// published its fp16 partials, then run the exact col_reduce body (same
// fixed-order fp32 combine -> bit-identical ev). Kills 50 launches.
//   E' = 1024*exp(-10*C) fp16, evh = ev/32 fp16.
//   phase1: rp_h2 += E'*evh -> 32*rowsum; eu = 32(d+eps)/rs
//   phase2: cacc_h2 += eu*E' (fp16 partial colsums)
//   tail:   ev = (s+eps)*1024/sum(partials); evh = ev/32
//   final:  P = (eu/1024)*E'*ev == eu*E*ev exactly (powers of 2)

#define NN 8192
#define NC4 (NN / 8)                 // 1024 uint4 chunks per row
#define GROWS 2
#define NGROUPS (NN / GROWS)         // 4096
#define NCTAS 296                    // 2 CTAs/SM x 148 SMs — ALL co-resident
#define NTHR 512
#define EPS 1e-6f
#define ESCALE 1024.0f
#define PERSIST_ROWS 5632

__device__ __align__(16) __half g_E[(size_t)NN * NN];          // 128 MB
__device__ __align__(16) float  g_eu[NN];                      // eu/1024 (final)
__device__ __align__(16) float  g_ev[NN];                      // fp32 ev (final)
__device__ __align__(16) __half g_evh[NN];                     // ev/32 (hot loop)
__device__ __align__(16) __half g_parth[(size_t)NCTAS * NN];   // 4.85 MB fp16
__device__ int g_ctr;                                          // completion ctr

// ---- L2 evict_last policy helpers -----------------------------------------
__device__ __forceinline__ uint64_t policy_evict_last() {
    uint64_t pol;
    asm("createpolicy.fractional.L2::evict_last.b64 %0, 1.0;" : "=l"(pol));
    return pol;
}
__device__ __forceinline__ uint4 ldg_pol(const uint4* p, uint64_t pol) {
    uint4 v;
    asm volatile("ld.global.L2::cache_hint.v4.b32 {%0,%1,%2,%3}, [%4], %5;"
                 : "=r"(v.x), "=r"(v.y), "=r"(v.z), "=r"(v.w)
                 : "l"(p), "l"(pol));
    return v;
}
__device__ __forceinline__ void stg_pol(uint4* p, uint4 v, uint64_t pol) {
    asm volatile("st.global.L2::cache_hint.v4.b32 [%0], {%1,%2,%3,%4}, %5;"
                 :: "l"(p), "r"(v.x), "r"(v.y), "r"(v.z), "r"(v.w), "l"(pol)
                 : "memory");
}

// FMA-only exp for x in [-15, 0]
__device__ __forceinline__ float fast_exp_neg(float x) {
    const float LOG2E = 1.4426950408889634f;
    float t = x * LOG2E;
    float n = rintf(t);
    float f = t - n;
    float p = 1.5403530393381608e-4f;
    p = fmaf(p, f, 1.3333558146428443e-3f);
    p = fmaf(p, f, 9.6181291076284770e-3f);
    p = fmaf(p, f, 5.5504108664821580e-2f);
    p = fmaf(p, f, 2.4022650695910070e-1f);
    p = fmaf(p, f, 6.9314718055994530e-1f);
    p = fmaf(p, f, 1.0f);
    return p * __int_as_float(((int)n + 127) << 23);
}

// ---------------------------------------------------------------------------
__global__ void precompute_kernel(const float* __restrict__ C) {
    size_t g = (size_t)blockIdx.x * blockDim.x + threadIdx.x;
    const float4* C4 = reinterpret_cast<const float4*>(C);
    float4 c0 = C4[2 * g];
    float4 c1 = C4[2 * g + 1];
    uint4 o;
    __half2* h = reinterpret_cast<__half2*>(&o);
    h[0] = __floats2half2_rn(ESCALE * fast_exp_neg(-10.0f * c0.x),
                             ESCALE * fast_exp_neg(-10.0f * c0.y));
    h[1] = __floats2half2_rn(ESCALE * fast_exp_neg(-10.0f * c0.z),
                             ESCALE * fast_exp_neg(-10.0f * c0.w));
    h[2] = __floats2half2_rn(ESCALE * fast_exp_neg(-10.0f * c1.x),
                             ESCALE * fast_exp_neg(-10.0f * c1.y));
    h[3] = __floats2half2_rn(ESCALE * fast_exp_neg(-10.0f * c1.z),
                             ESCALE * fast_exp_neg(-10.0f * c1.w));
    uint4* dst = reinterpret_cast<uint4*>(g_E) + g;
    int row = (int)(g >> 10);
    if (row < PERSIST_ROWS) {
        stg_pol(dst, o, policy_evict_last());
    } else {
        *dst = o;
    }
    if (g < NN) {
        const float E1 = 2.718281828459045f;     // exp(v0), v0 = 1
        g_ev[g]  = E1;
        g_evh[g] = __float2half_rn(E1 * 0.03125f);
    }
    if (g == 0) g_ctr = 0;            // deterministic across graph replays
}

// ---------------------------------------------------------------------------
// Fused iteration + column reduction: 296 CTAs x 512 threads, 2 CTAs/SM.
// Thread t owns chunks t and t+512 of each row. 1 barrier per 2-row group.
// ---------------------------------------------------------------------------
__global__ void __launch_bounds__(NTHR, 2)
iter_kernel(const float* __restrict__ d, const float* __restrict__ s,
            int target) {
    __shared__ float wpart[64];       // [2 parities][32]
    __shared__ float red[8][32][8];   // reduction scratch (CTAs 0..31 only)

    const int tid  = threadIdx.x;
    const int wid  = tid >> 5;
    const int lane = tid & 31;
    const int cta  = blockIdx.x;
    const int ng   = (NGROUPS - cta + NCTAS - 1) / NCTAS;      // 13 or 14

    const uint4* Eg  = reinterpret_cast<const uint4*>(g_E);
    const uint4* EVH = reinterpret_cast<const uint4*>(g_evh);
    const uint64_t pol = policy_evict_last();

    // ev/32 for this thread's 16 columns (8 half2 regs, loop-invariant)
    __half2 va2[4], vb2[4];
    {
        uint4 v = __ldg(EVH + tid);
        const __half2* hv = reinterpret_cast<const __half2*>(&v);
#pragma unroll
        for (int k = 0; k < 4; ++k) va2[k] = hv[k];
        v = __ldg(EVH + tid + 512);
        hv = reinterpret_cast<const __half2*>(&v);
#pragma unroll
        for (int k = 0; k < 4; ++k) vb2[k] = hv[k];
    }

    __half2 cacc[8];
#pragma unroll
    for (int k = 0; k < 8; ++k) cacc[k] = __float2half2_rn(0.0f);

    uint4 xA0, xB0, xA1, xB1;         // current buffer
    uint4 yA0, yB0, yA1, yB1;         // next buffer

    auto loadg = [&](int t, uint4& a0, uint4& b0, uint4& a1, uint4& b1) {
        const int grow0 = (cta + t * NCTAS) * GROWS;
        const uint4* s0 = Eg + (size_t)grow0 * NC4;
        const uint4* s1 = s0 + NC4;
        if (grow0 < PERSIST_ROWS) {
            a0 = ldg_pol(s0 + tid, pol);
            b0 = ldg_pol(s0 + tid + 512, pol);
            a1 = ldg_pol(s1 + tid, pol);
            b1 = ldg_pol(s1 + tid + 512, pol);
        } else {
            a0 = __ldcs(s0 + tid);
            b0 = __ldcs(s0 + tid + 512);
            a1 = __ldcs(s1 + tid);
            b1 = __ldcs(s1 + tid + 512);
        }
    };

    auto process = [&](int t, const uint4& eA0, const uint4& eB0,
                              const uint4& eA1, const uint4& eB1) {
        const int grow0 = (cta + t * NCTAS) * GROWS;
        float* wp = wpart + (t & 1) * 32;
        const __half2* a0 = reinterpret_cast<const __half2*>(&eA0);
        const __half2* b0 = reinterpret_cast<const __half2*>(&eB0);
        const __half2* a1 = reinterpret_cast<const __half2*>(&eA1);
        const __half2* b1 = reinterpret_cast<const __half2*>(&eB1);

        // ---- phase 1: rowsum partials in HFMA2 ----------------------------
        __half2 rp0 = __float2half2_rn(0.0f);
        __half2 rp1 = __float2half2_rn(0.0f);
#pragma unroll
        for (int k = 0; k < 4; ++k) {
            rp0 = __hfma2(a0[k], va2[k], rp0);
            rp0 = __hfma2(b0[k], vb2[k], rp0);
            rp1 = __hfma2(a1[k], va2[k], rp1);
            rp1 = __hfma2(b1[k], vb2[k], rp1);
        }
        float2 f0 = __half22float2(rp0);
        float2 f1 = __half22float2(rp1);
        float s0 = f0.x + f0.y;
        float s1 = f1.x + f1.y;
#pragma unroll
        for (int o = 16; o > 0; o >>= 1) {
            s0 += __shfl_down_sync(0xFFFFFFFFu, s0, o);
            s1 += __shfl_down_sync(0xFFFFFFFFu, s1, o);
        }
        if (lane == 0) {
            wp[wid]      = s0;
            wp[16 + wid] = s1;
        }
        __syncthreads();              // the only barrier in the group

        // ---- xor-butterfly over the 32 warp partials (fixed tree) ---------
        float v = wp[lane];
#pragma unroll
        for (int o = 1; o < 16; o <<= 1)
            v += __shfl_xor_sync(0xFFFFFFFFu, v, o);
        float w = __shfl_xor_sync(0xFFFFFFFFu, v, 16);
        float rs0 = (lane < 16) ? v : w;
        float rs1 = (lane < 16) ? w : v;
        float eu0 = __fdividef((__ldg(d + grow0)     + EPS) * 32.0f, rs0);
        float eu1 = __fdividef((__ldg(d + grow0 + 1) + EPS) * 32.0f, rs1);
        if (tid == 0) {
            g_eu[grow0]     = eu0 * (1.0f / 1024.0f);
            g_eu[grow0 + 1] = eu1 * (1.0f / 1024.0f);
        }

        // ---- phase 2: fp16 column accumulation ----------------------------
        __half2 u0 = __float2half2_rn(eu0);
        __half2 u1 = __float2half2_rn(eu1);
#pragma unroll
        for (int k = 0; k < 4; ++k) {
            cacc[k]     = __hfma2(a0[k], u0, cacc[k]);
            cacc[4 + k] = __hfma2(b0[k], u0, cacc[4 + k]);
            cacc[k]     = __hfma2(a1[k], u1, cacc[k]);
            cacc[4 + k] = __hfma2(b1[k], u1, cacc[4 + k]);
        }
    };

    loadg(0, xA0, xB0, xA1, xB1);
    for (int t = 0; t < ng; t += 2) {
        if (t + 1 < ng) loadg(t + 1, yA0, yB0, yA1, yB1);
        process(t, xA0, xB0, xA1, xB1);
        if (t + 1 < ng) {
            if (t + 2 < ng) loadg(t + 2, xA0, xB0, xA1, xB1);
            process(t + 1, yA0, yB0, yA1, yB1);
        }
    }

    // write fp16 partials (streaming stores)
    uint4 o0, o1;
    __half2* p0 = reinterpret_cast<__half2*>(&o0);
    __half2* p1 = reinterpret_cast<__half2*>(&o1);
#pragma unroll
    for (int k = 0; k < 4; ++k) { p0[k] = cacc[k]; p1[k] = cacc[4 + k]; }
    uint4* PH = reinterpret_cast<uint4*>(g_parth + (size_t)cta * NN);
    __stcs(PH + tid,       o0);
    __stcs(PH + tid + 512, o1);

    // ---- completion protocol (threadFenceReduction pattern) ---------------
    __threadfence();                  // each thread's partials visible GPU-wide
    __syncthreads();                  // all threads' stores fenced
    if (tid == 0) atomicAdd(&g_ctr, 1);

    // ---- fused column reduction: CTAs 0..31 (all 296 CTAs co-resident) ----
    if (cta < 32) {
        if (tid == 0) {
            volatile int* c = &g_ctr;
            while (*c < target) __nanosleep(64);
        }
        __syncthreads();              // counter observation -> whole CTA

        const bool active = tid < 256;
        const int gg    = tid & 31;
        const int slice = (tid >> 5) & 7;
        const int chunk = cta * 32 + gg;         // 0..1023 (8 cols each)
        float acc[8] = {0.f, 0.f, 0.f, 0.f, 0.f, 0.f, 0.f, 0.f};
        if (active) {
            const uint4* PHall = reinterpret_cast<const uint4*>(g_parth);
#pragma unroll
            for (int k = 0; k < 37; ++k) {
                uint4 v = __ldcs(PHall + (size_t)(slice * 37 + k) * NC4 + chunk);
                const __half2* h = reinterpret_cast<const __half2*>(&v);
#pragma unroll
                for (int m = 0; m < 4; ++m) {
                    float2 f = __half22float2(h[m]);
                    acc[2 * m]     += f.x;
                    acc[2 * m + 1] += f.y;
                }
            }
#pragma unroll
            for (int m = 0; m < 8; ++m) red[slice][gg][m] = acc[m];
        }
        __syncthreads();
        if (active && slice == 0) {
            float tv[8];
#pragma unroll
            for (int m = 0; m < 8; ++m) tv[m] = red[0][gg][m];
#pragma unroll
            for (int q = 1; q < 8; ++q)             // fixed order
#pragma unroll
                for (int m = 0; m < 8; ++m) tv[m] += red[q][gg][m];
            const int j0 = chunk * 8;
            float ev[8];
#pragma unroll
            for (int m = 0; m < 8; ++m)
                ev[m] = (s[j0 + m] + EPS) * 1024.0f / tv[m];
            float4* EV4 = reinterpret_cast<float4*>(g_ev + j0);
            EV4[0] = make_float4(ev[0], ev[1], ev[2], ev[3]);
            EV4[1] = make_float4(ev[4], ev[5], ev[6], ev[7]);
            uint4 hv;
            __half2* hp = reinterpret_cast<__half2*>(&hv);
#pragma unroll
            for (int m = 0; m < 4; ++m)
                hp[m] = __floats2half2_rn(ev[2 * m] * 0.03125f,
                                          ev[2 * m + 1] * 0.03125f);
            *reinterpret_cast<uint4*>(g_evh + j0) = hv;
        }
    }
}

// ---------------------------------------------------------------------------
// Final: P_ij = (eu_i/1024) * E'_ij * ev_j   (fp32 eu/ev)
// ---------------------------------------------------------------------------
__global__ void final_kernel(float* __restrict__ out) {
    size_t idx = (size_t)blockIdx.x * blockDim.x + threadIdx.x;
    int row = (int)(idx / NC4);
    int c8  = (int)(idx % NC4);
    float u = g_eu[row];
    const float4* ev4 = reinterpret_cast<const float4*>(g_ev);
    float4 v0 = ev4[2 * c8];
    float4 v1 = ev4[2 * c8 + 1];
    uint4 e = __ldg(reinterpret_cast<const uint4*>(g_E) + idx);
    const __half2* hp = reinterpret_cast<const __half2*>(&e);
    float2 f0 = __half22float2(hp[0]);
    float2 f1 = __half22float2(hp[1]);
    float2 f2 = __half22float2(hp[2]);
    float2 f3 = __half22float2(hp[3]);
    float4 p0, p1;
    p0.x = u * f0.x * v0.x;  p0.y = u * f0.y * v0.y;
    p0.z = u * f1.x * v0.z;  p0.w = u * f1.y * v0.w;
    p1.x = u * f2.x * v1.x;  p1.y = u * f2.y * v1.y;
    p1.z = u * f3.x * v1.z;  p1.w = u * f3.y * v1.w;
    float4* O4 = reinterpret_cast<float4*>(out);
    O4[2 * idx]     = p0;
    O4[2 * idx + 1] = p1;
}

// ---------------------------------------------------------------------------
extern "C" void kernel_launch(void* const* d_in, const int* in_sizes, int n_in,
                              void* d_out, int out_size) {
    const float* C = (const float*)d_in[0];
    const float* d = (const float*)d_in[1];
    const float* s = (const float*)d_in[2];
    float* out = (float*)d_out;

    const int VBLOCKS = (NN * NC4) / 256;    // 32768

    precompute_kernel<<<VBLOCKS, 256>>>(C);  // also resets g_ctr

    for (int it = 0; it < 50; ++it) {
        iter_kernel<<<NCTAS, NTHR>>>(d, s, (it + 1) * NCTAS);
    }

    final_kernel<<<VBLOCKS, 256>>>(out);
}